// round 10
// baseline (speedup 1.0000x reference)
#include <cuda_runtime.h>
#include <cstddef>

#define BATCH    256
#define DATA_DIM 8192
#define NNZ      256
#define QK       64
#define EMB      63
#define NSUB     8
#define WTS      68
#define K0S      260   // staging stride; conflict-free for row STS, 4-way on one-time column LDS

typedef unsigned long long u64;

// Precomputed per-row projections of the embedding table (row 0 = padding row).
__device__ float4 g_Q0T[(DATA_DIM + 1) * 16];
__device__ float4 g_K0T[(DATA_DIM + 1) * 16];

__device__ __forceinline__ void fma2(u64& acc, u64 a, u64 b) {
    asm("fma.rn.f32x2 %0, %1, %2, %0;" : "+l"(acc) : "l"(a), "l"(b));
}
__device__ __forceinline__ u64 fma2n(u64 a, u64 b, u64 c) {
    u64 d;
    asm("fma.rn.f32x2 %0, %1, %2, %3;" : "=l"(d) : "l"(a), "l"(b), "l"(c));
    return d;
}
__device__ __forceinline__ float hsum2(u64 a) {
    return __uint_as_float((unsigned)a) + __uint_as_float((unsigned)(a >> 32));
}
__device__ __forceinline__ u64 pack2(float lo, float hi) {
    u64 r;
    asm("mov.b64 %0, {%1, %2};" : "=l"(r) : "f"(lo), "f"(hi));
    return r;
}

// ---------------------------------------------------------------------------
// Kernel P: 257 blocks x 32 table rows (proven numerics).
// Q0T[p][d] = bq[d] + sum_e embed[p][e] * Wq[d][e+1]   (same for K)
// ---------------------------------------------------------------------------
__global__ void __launch_bounds__(256)
precompute_kernel(const float* __restrict__ embed,
                  const float* __restrict__ Wq,
                  const float* __restrict__ bq,
                  const float* __restrict__ Wk,
                  const float* __restrict__ bk) {
    __shared__ __align__(16) float WqT[64 * WTS];
    __shared__ __align__(16) float WkT[64 * WTS];
    __shared__ __align__(16) float es[32][64];

    const int tid = threadIdx.x;
    for (int i = tid; i < 4096; i += 256) {
        int d = i >> 6, e = i & 63;
        WqT[e * WTS + d] = Wq[i];
        WkT[e * WTS + d] = Wk[i];
    }
    const int p0 = blockIdx.x * 32;
    for (int i = tid; i < 32 * 63; i += 256) {
        int r = i / 63, e = i - r * 63;
        int p = p0 + r;
        es[r][e] = (p <= DATA_DIM) ? embed[(size_t)p * EMB + e] : 0.0f;
    }
    __syncthreads();

    const int rl = tid >> 4, d4 = tid & 15;
    const float4 bq4 = __ldg(reinterpret_cast<const float4*>(bq) + d4);
    const float4 bk4 = __ldg(reinterpret_cast<const float4*>(bk) + d4);
#pragma unroll
    for (int grp = 0; grp < 2; ++grp) {
        const int r = grp * 16 + rl;
        const int p = p0 + r;
        if (p <= DATA_DIM) {
            float4 aq = bq4, ak = bk4;
#pragma unroll 9
            for (int e = 0; e < EMB; ++e) {
                float ev = es[r][e];
                float4 wq = *reinterpret_cast<const float4*>(&WqT[(e + 1) * WTS + 4 * d4]);
                float4 wk = *reinterpret_cast<const float4*>(&WkT[(e + 1) * WTS + 4 * d4]);
                aq.x += ev * wq.x; aq.y += ev * wq.y; aq.z += ev * wq.z; aq.w += ev * wq.w;
                ak.x += ev * wk.x; ak.y += ev * wk.y; ak.z += ev * wk.z; ak.w += ev * wk.w;
            }
            g_Q0T[(size_t)p * 16 + d4] = aq;
            g_K0T[(size_t)p * 16 + d4] = ak;
        }
    }
}

// ---------------------------------------------------------------------------
// Kernel C: 256 threads, 1 block/SM, all matrix data register-resident.
// Segmented-warp s-computation: warp w owns d in [8w,8w+8); lane (d, jq)
// holds k0[64jq..64jq+64)[d]. 3 barriers + 1 tree per eval.
// ---------------------------------------------------------------------------
struct SmemC {
    __align__(16) float k0s[64 * K0S];  // transient staging
    __align__(16) float wsh[NNZ];
    __align__(16) float ssh[QK];
    __align__(16) float ash[QK];        // a = Wq[:,0]
    __align__(16) float red2[8];        // per-warp w*f partials
    __align__(16) float val[NNZ];
    int   idx[NNZ];
    int   wscan[8];
};

extern __shared__ unsigned char smem_raw[];

__global__ void __launch_bounds__(256, 1)
integrate_kernel(const float* __restrict__ t,
                 const float* __restrict__ x,
                 const float* __restrict__ Wq,
                 const float* __restrict__ Wk,
                 float* __restrict__ out) {
    SmemC* sm = reinterpret_cast<SmemC*>(smem_raw);
    const int tid  = threadIdx.x;
    const int b    = blockIdx.x;
    const int lane = tid & 31;
    const int wid  = tid >> 5;

    // ---- Phase 0: zero this block's two output rows ----
    {
        float4 z = make_float4(0.f, 0.f, 0.f, 0.f);
        float4* o4 = reinterpret_cast<float4*>(out);
        for (int i = tid; i < 2048; i += 256) {
            o4[(size_t)b * 2048 + i] = z;
            o4[(size_t)(BATCH + b) * 2048 + i] = z;
        }
    }

    // ---- Phase 1: scan + order-preserving compaction ----
    float xr[32];
    {
        const float4* xrow4 = reinterpret_cast<const float4*>(x + (size_t)b * DATA_DIM) + tid * 8;
#pragma unroll
        for (int j = 0; j < 8; ++j) {
            float4 f = xrow4[j];
            xr[4 * j + 0] = f.x; xr[4 * j + 1] = f.y;
            xr[4 * j + 2] = f.z; xr[4 * j + 3] = f.w;
        }
    }
    if (tid < NNZ) { sm->val[tid] = 0.0f; sm->idx[tid] = 0; }

    int cnt = 0;
#pragma unroll
    for (int j = 0; j < 32; ++j) cnt += (xr[j] != 0.0f) ? 1 : 0;
    int inc = cnt;
#pragma unroll
    for (int o = 1; o < 32; o <<= 1) {
        int u = __shfl_up_sync(0xffffffffu, inc, o);
        if (lane >= o) inc += u;
    }
    if (lane == 31) sm->wscan[wid] = inc;
    __syncthreads();
    int woff = 0;
#pragma unroll
    for (int wdx = 0; wdx < 8; ++wdx) woff += (wdx < wid) ? sm->wscan[wdx] : 0;
    int o = woff + inc - cnt;
#pragma unroll
    for (int j = 0; j < 32; ++j) {
        float v = xr[j];
        if (v != 0.0f && o < NNZ) {
            sm->val[o] = v;
            sm->idx[o] = tid * 32 + j;
            ++o;
        }
    }
    __syncthreads();

    // ---- Phase 2: gathers ----
    const int p     = sm->idx[tid] + 1;
    const float myv = sm->val[tid];

    out[(size_t)b * DATA_DIM + (p - 1)] = myv;   // t=0 plane

    // my q0 row (64 floats as 32 packed pairs) -> registers
    u64 q0r[32];
    {
        const ulonglong2* qrow = reinterpret_cast<const ulonglong2*>(g_Q0T + (size_t)p * 16);
#pragma unroll
        for (int i = 0; i < 16; ++i) {
            ulonglong2 v = qrow[i];
            q0r[2 * i] = v.x; q0r[2 * i + 1] = v.y;
        }
        // stage my k0 row -> shared, transposed [d][i]
        const float4* krow = g_K0T + (size_t)p * 16;
#pragma unroll
        for (int i = 0; i < 16; ++i) {
            float4 f = krow[i];
            int d = 4 * i;
            sm->k0s[(d + 0) * K0S + tid] = f.x;
            sm->k0s[(d + 1) * K0S + tid] = f.y;
            sm->k0s[(d + 2) * K0S + tid] = f.z;
            sm->k0s[(d + 3) * K0S + tid] = f.w;
        }
    }

    // a = Wq[:,0] -> shared (used as broadcast pairs in the q-loop)
    if (tid < QK) sm->ash[tid] = Wq[tid * 64];

    // segmented role: d = 8*wid + (lane>>2), jq = lane&3
    const int dsg = 8 * wid + (lane >> 2);
    const int jq  = lane & 3;
    const float bvd = Wk[dsg * 64];     // b_d for my segment row

    const float dt = (t[1] - t[0]) * (1.0f / (float)NSUB);

    sm->wsh[tid] = myv;
    __syncthreads();    // staging + ash + wsh all visible

    // my k0 column chunk: k0[64jq .. 64jq+64)[dsg] -> 32 packed pairs
    u64 k0c[32];
    {
        const ulonglong2* ksrc =
            reinterpret_cast<const ulonglong2*>(sm->k0s + dsg * K0S + 64 * jq);
#pragma unroll
        for (int k = 0; k < 16; ++k) {
            ulonglong2 v = ksrc[k];
            k0c[2 * k] = v.x; k0c[2 * k + 1] = v.y;
        }
    }

    const ulonglong2* wvp = reinterpret_cast<const ulonglong2*>(sm->wsh + 64 * jq);
    const u64* svp = reinterpret_cast<const u64*>(sm->ssh);
    const u64* avp = reinterpret_cast<const u64*>(sm->ash);

    // dxdt(w): s_d = S2*b_d + (K0^T w)_d  (computed segmented per warp);
    // f_i = sum_d (a_d*w_i + q0_id)*s_d / 8;  g = sum_i w_i f_i.
    // precondition: wsh staged + synced.
    auto dxdt = [&](float w) -> float {
        // m_d and S2 partials over my 64-j chunk (register FMAs, broadcast w)
        u64 m0 = 0ull, m1 = 0ull, s0 = 0ull, s1 = 0ull;
#pragma unroll
        for (int k = 0; k < 16; ++k) {
            ulonglong2 wv = wvp[k];
            fma2(m0, k0c[2 * k], wv.x);
            fma2(m1, k0c[2 * k + 1], wv.y);
            fma2(s0, wv.x, wv.x);
            fma2(s1, wv.y, wv.y);
        }
        float mp  = hsum2(m0) + hsum2(m1);
        float s2p = hsum2(s0) + hsum2(s1);
        // butterfly over the 4 jq lanes of my d-group: ((p0+p1)+(p2+p3))
        mp  += __shfl_xor_sync(0xffffffffu, mp, 1);
        s2p += __shfl_xor_sync(0xffffffffu, s2p, 1);
        mp  += __shfl_xor_sync(0xffffffffu, mp, 2);
        s2p += __shfl_xor_sync(0xffffffffu, s2p, 2);
        if (jq == 0) sm->ssh[dsg] = fmaf(s2p, bvd, mp);
        __syncthreads();                                   // BAR 1: s ready

        // f_i with a folded in: acc += (a*w + q0) * s
        u64 wpk = pack2(w, w);
        u64 q0 = 0ull, q1 = 0ull;
#pragma unroll
        for (int k = 0; k < 16; ++k) {
            fma2(q0, fma2n(avp[2 * k],     wpk, q0r[2 * k]),     svp[2 * k]);
            fma2(q1, fma2n(avp[2 * k + 1], wpk, q0r[2 * k + 1]), svp[2 * k + 1]);
        }
        float f = (hsum2(q0) + hsum2(q1)) * 0.125f;        // 1/sqrt(64)

        float wf = w * f;
#pragma unroll
        for (int o2 = 16; o2 > 0; o2 >>= 1) wf += __shfl_xor_sync(0xffffffffu, wf, o2);
        if (lane == 0) sm->red2[wid] = wf;
        __syncthreads();                                   // BAR 2: g partials
        float4 r2a = *reinterpret_cast<const float4*>(&sm->red2[0]);
        float4 r2b = *reinterpret_cast<const float4*>(&sm->red2[4]);
        float g = (r2a.x + r2a.y) + (r2a.z + r2a.w) + (r2b.x + r2b.y) + (r2b.z + r2b.w);

        return w * (f - g);
    };

    float vcur = myv;

    // ---- Phase 3: 8 RK4 substeps over [t0, t1] ----
    for (int stp = 0; stp < NSUB; ++stp) {
        float k1 = dxdt(vcur);
        float w2s = vcur + 0.5f * dt * k1;
        sm->wsh[tid] = w2s; __syncthreads();               // BAR 3 (stage)
        float k2 = dxdt(w2s);
        float w3s = vcur + 0.5f * dt * k2;
        sm->wsh[tid] = w3s; __syncthreads();
        float k3 = dxdt(w3s);
        float w4s = vcur + dt * k3;
        sm->wsh[tid] = w4s; __syncthreads();
        float k4 = dxdt(w4s);
        vcur += dt * (1.0f / 6.0f) * (k1 + 2.0f * k2 + 2.0f * k3 + k4);
        sm->wsh[tid] = vcur; __syncthreads();
    }

    // t=1 plane
    out[(size_t)BATCH * DATA_DIM + (size_t)b * DATA_DIM + (p - 1)] = vcur;
}

// ---------------------------------------------------------------------------
// kernel_launch
// ---------------------------------------------------------------------------
extern "C" void kernel_launch(void* const* d_in, const int* in_sizes, int n_in,
                              void* d_out, int out_size) {
    const float* t     = (const float*)d_in[0];
    const float* x     = (const float*)d_in[1];
    const float* embed = (const float*)d_in[2];
    const float* Wq    = (const float*)d_in[3];
    const float* bq    = (const float*)d_in[4];
    const float* Wk    = (const float*)d_in[5];
    const float* bk    = (const float*)d_in[6];
    float* out = (float*)d_out;

    cudaFuncSetAttribute(integrate_kernel,
                         cudaFuncAttributeMaxDynamicSharedMemorySize,
                         (int)sizeof(SmemC));

    precompute_kernel<<<(DATA_DIM + 1 + 31) / 32, 256>>>(embed, Wq, bq, Wk, bk);
    integrate_kernel<<<BATCH, 256, sizeof(SmemC)>>>(t, x, Wq, Wk, out);
}

// round 11
// speedup vs baseline: 1.7624x; 1.7624x over previous
#include <cuda_runtime.h>
#include <cstddef>

#define BATCH    256
#define DATA_DIM 8192
#define NNZ      256
#define QK       64
#define EMB      63
#define NSUB     8
#define WTS      68
#define WPS      68    // padded stride for w staging segments (4 banks apart -> conflict-free)

typedef unsigned long long u64;

// Precomputed per-row projections of the embedding table (row 0 = padding row).
__device__ float4 g_Q0T[(DATA_DIM + 1) * 16];
__device__ float4 g_K0T[(DATA_DIM + 1) * 16];

// packed f32x2 FMA: acc = a*b + acc
__device__ __forceinline__ void fma2(u64& acc, u64 a, u64 b) {
    asm("fma.rn.f32x2 %0, %1, %2, %0;" : "+l"(acc) : "l"(a), "l"(b));
}
__device__ __forceinline__ float hsum2(u64 a) {
    return __uint_as_float((unsigned)a) + __uint_as_float((unsigned)(a >> 32));
}
__device__ __forceinline__ u64 pack2(float lo, float hi) {
    u64 r;
    asm("mov.b64 %0, {%1, %2};" : "=l"(r) : "f"(lo), "f"(hi));
    return r;
}

// ---------------------------------------------------------------------------
// Kernel P: 257 blocks x 32 table rows (proven numerics).
// Q0T[p][d] = bq[d] + sum_e embed[p][e] * Wq[d][e+1]   (same for K)
// ---------------------------------------------------------------------------
__global__ void __launch_bounds__(256)
precompute_kernel(const float* __restrict__ embed,
                  const float* __restrict__ Wq,
                  const float* __restrict__ bq,
                  const float* __restrict__ Wk,
                  const float* __restrict__ bk) {
    __shared__ __align__(16) float WqT[64 * WTS];
    __shared__ __align__(16) float WkT[64 * WTS];
    __shared__ __align__(16) float es[32][64];

    const int tid = threadIdx.x;
    for (int i = tid; i < 4096; i += 256) {
        int d = i >> 6, e = i & 63;
        WqT[e * WTS + d] = Wq[i];
        WkT[e * WTS + d] = Wk[i];
    }
    const int p0 = blockIdx.x * 32;
    for (int i = tid; i < 32 * 63; i += 256) {
        int r = i / 63, e = i - r * 63;
        int p = p0 + r;
        es[r][e] = (p <= DATA_DIM) ? embed[(size_t)p * EMB + e] : 0.0f;
    }
    __syncthreads();

    const int rl = tid >> 4, d4 = tid & 15;
    const float4 bq4 = __ldg(reinterpret_cast<const float4*>(bq) + d4);
    const float4 bk4 = __ldg(reinterpret_cast<const float4*>(bk) + d4);
#pragma unroll
    for (int grp = 0; grp < 2; ++grp) {
        const int r = grp * 16 + rl;
        const int p = p0 + r;
        if (p <= DATA_DIM) {
            float4 aq = bq4, ak = bk4;
#pragma unroll 9
            for (int e = 0; e < EMB; ++e) {
                float ev = es[r][e];
                float4 wq = *reinterpret_cast<const float4*>(&WqT[(e + 1) * WTS + 4 * d4]);
                float4 wk = *reinterpret_cast<const float4*>(&WkT[(e + 1) * WTS + 4 * d4]);
                aq.x += ev * wq.x; aq.y += ev * wq.y; aq.z += ev * wq.z; aq.w += ev * wq.w;
                ak.x += ev * wk.x; ak.y += ev * wk.y; ak.z += ev * wk.z; ak.w += ev * wk.w;
            }
            g_Q0T[(size_t)p * 16 + d4] = aq;
            g_K0T[(size_t)p * 16 + d4] = ak;
        }
    }
}

// ---------------------------------------------------------------------------
// Kernel C: R6/R7 hybrid. 256 threads, 1 block/SM (no reg cap, no spill).
// q0 row + k0 column both register-resident; R7's coalesced LDG k0 gather;
// PADDED w staging (segments 4 banks apart -> conflict-free m-loop LDS.128).
// Reduction ordering bit-identical to R6/R7.
// ---------------------------------------------------------------------------
__global__ void __launch_bounds__(256, 1)
integrate_kernel(const float* __restrict__ t,
                 const float* __restrict__ x,
                 const float* __restrict__ Wq,
                 const float* __restrict__ Wk,
                 float* __restrict__ out) {
    __shared__ __align__(16) float wsh[4 * WPS];   // padded w staging
    __shared__ __align__(16) float ssh[QK];
    __shared__ __align__(16) float mpart[256];
    __shared__ __align__(16) float red1[8];        // per-warp w^2 partials
    __shared__ __align__(16) float red2[8];        // per-warp w*f partials
    __shared__ __align__(16) float c1p[2];         // a.s partials
    __shared__ __align__(16) float val[NNZ];
    __shared__ int idx[NNZ];
    __shared__ int wscan[8];

    const int tid  = threadIdx.x;
    const int b    = blockIdx.x;
    const int lane = tid & 31;
    const int wid  = tid >> 5;

    // ---- Phase 0: zero this block's two output rows ----
    {
        float4 z = make_float4(0.f, 0.f, 0.f, 0.f);
        float4* o4 = reinterpret_cast<float4*>(out);
        for (int i = tid; i < 2048; i += 256) {
            o4[(size_t)b * 2048 + i] = z;
            o4[(size_t)(BATCH + b) * 2048 + i] = z;
        }
    }

    // ---- Phase 1: scan + order-preserving compaction ----
    float xr[32];
    {
        const float4* xrow4 = reinterpret_cast<const float4*>(x + (size_t)b * DATA_DIM) + tid * 8;
#pragma unroll
        for (int j = 0; j < 8; ++j) {
            float4 f = xrow4[j];
            xr[4 * j + 0] = f.x; xr[4 * j + 1] = f.y;
            xr[4 * j + 2] = f.z; xr[4 * j + 3] = f.w;
        }
    }
    if (tid < NNZ) { val[tid] = 0.0f; idx[tid] = 0; }

    int cnt = 0;
#pragma unroll
    for (int j = 0; j < 32; ++j) cnt += (xr[j] != 0.0f) ? 1 : 0;
    int inc = cnt;
#pragma unroll
    for (int o = 1; o < 32; o <<= 1) {
        int u = __shfl_up_sync(0xffffffffu, inc, o);
        if (lane >= o) inc += u;
    }
    if (lane == 31) wscan[wid] = inc;
    __syncthreads();
    int woff = 0;
#pragma unroll
    for (int wdx = 0; wdx < 8; ++wdx) woff += (wdx < wid) ? wscan[wdx] : 0;
    int o = woff + inc - cnt;
#pragma unroll
    for (int j = 0; j < 32; ++j) {
        float v = xr[j];
        if (v != 0.0f && o < NNZ) {
            val[o] = v;
            idx[o] = tid * 32 + j;
            ++o;
        }
    }
    __syncthreads();

    // ---- Phase 2: q0 row -> regs; k0 column -> regs via coalesced LDG ----
    const int p     = idx[tid] + 1;
    const float myv = val[tid];

    out[(size_t)b * DATA_DIM + (p - 1)] = myv;   // t=0 plane

    u64 q0p[32];   // my row of Q0 (64 floats as 32 packed pairs, sequential)
    {
        const ulonglong2* qrow = reinterpret_cast<const ulonglong2*>(g_Q0T + (size_t)p * 16);
#pragma unroll
        for (int i = 0; i < 16; ++i) {
            ulonglong2 v = qrow[i];
            q0p[2 * i] = v.x; q0p[2 * i + 1] = v.y;
        }
    }

    const int dd = tid & 63, cc = tid >> 6;

    // k0 column chunk K0[p_j][dd], j in [64cc, 64cc+64) -> 32 packed pairs
    // (uniform j per iteration -> each LDG is one 128B sector across the warp)
    u64 k0u[32];
    {
        const float* k0g = reinterpret_cast<const float*>(g_K0T);
        const int jb = cc * 64;
#pragma unroll
        for (int j = 0; j < 32; ++j) {
            int pa = idx[jb + 2 * j] + 1;
            int pb = idx[jb + 2 * j + 1] + 1;
            float fa = __ldg(k0g + (size_t)pa * 64 + dd);
            float fb = __ldg(k0g + (size_t)pb * 64 + dd);
            k0u[j] = pack2(fa, fb);
        }
    }

    float avd = 0.0f, bvd = 0.0f;
    if (tid < QK) { avd = Wq[tid * 64]; bvd = Wk[tid * 64]; }

    const float dt = (t[1] - t[0]) * (1.0f / (float)NSUB);
    const ulonglong2* wvp = reinterpret_cast<const ulonglong2*>(wsh + cc * WPS);
    const ulonglong2* svp = reinterpret_cast<const ulonglong2*>(ssh);

    // stage: publish w (padded segment layout) + per-warp w^2 partial.
    // caller must __syncthreads() after.
    auto stage = [&](float w) {
        wsh[cc * WPS + dd] = w;
        float w2 = w * w;
#pragma unroll
        for (int o2 = 16; o2 > 0; o2 >>= 1) w2 += __shfl_xor_sync(0xffffffffu, w2, o2);
        if (lane == 0) red1[wid] = w2;
    };

    // dxdt(w) = w*(f - g);  s = S2*b + K0^T w;  f_i = (c1*w_i + q0_i.s)/8;
    // c1 = a.s;  g = sum_j w_j f_j.  precondition: stage(w) + sync done.
    auto dxdt = [&](float w) -> float {
        u64 a0 = 0ull, a1 = 0ull;
#pragma unroll
        for (int m = 0; m < 16; ++m) {
            ulonglong2 wv = wvp[m];
            fma2(a0, k0u[2 * m], wv.x);
            fma2(a1, k0u[2 * m + 1], wv.y);
        }
        mpart[tid] = hsum2(a0) + hsum2(a1);
        __syncthreads();                                   // BAR A

        if (tid < QK) {
            float4 r1a = *reinterpret_cast<const float4*>(&red1[0]);
            float4 r1b = *reinterpret_cast<const float4*>(&red1[4]);
            float S2 = (r1a.x + r1a.y) + (r1a.z + r1a.w) + (r1b.x + r1b.y) + (r1b.z + r1b.w);
            float m = mpart[tid] + mpart[tid + 64] +
                      mpart[tid + 128] + mpart[tid + 192];
            float sv = S2 * bvd + m;
            ssh[tid] = sv;
            float cp = avd * sv;
#pragma unroll
            for (int o2 = 16; o2 > 0; o2 >>= 1) cp += __shfl_xor_sync(0xffffffffu, cp, o2);
            if (lane == 0) c1p[wid] = cp;                  // wid = 0 or 1
        }
        __syncthreads();                                   // BAR B

        u64 q0 = 0ull, q1 = 0ull;
#pragma unroll
        for (int m = 0; m < 16; ++m) {
            ulonglong2 sv = svp[m];
            fma2(q0, q0p[2 * m], sv.x);
            fma2(q1, q0p[2 * m + 1], sv.y);
        }
        float qdot = hsum2(q0) + hsum2(q1);
        float c1 = c1p[0] + c1p[1];
        float f  = (c1 * w + qdot) * 0.125f;               // 1/sqrt(64)

        float wf = w * f;
#pragma unroll
        for (int o2 = 16; o2 > 0; o2 >>= 1) wf += __shfl_xor_sync(0xffffffffu, wf, o2);
        if (lane == 0) red2[wid] = wf;
        __syncthreads();                                   // BAR C
        float4 r2a = *reinterpret_cast<const float4*>(&red2[0]);
        float4 r2b = *reinterpret_cast<const float4*>(&red2[4]);
        float g = (r2a.x + r2a.y) + (r2a.z + r2a.w) + (r2b.x + r2b.y) + (r2b.z + r2b.w);

        return w * (f - g);
    };

    float vcur = myv;
    stage(vcur);
    __syncthreads();

    // ---- Phase 3: 8 RK4 substeps over [t0, t1] ----
    for (int stp = 0; stp < NSUB; ++stp) {
        float k1 = dxdt(vcur);
        float w2s = vcur + 0.5f * dt * k1;
        stage(w2s); __syncthreads();
        float k2 = dxdt(w2s);
        float w3s = vcur + 0.5f * dt * k2;
        stage(w3s); __syncthreads();
        float k3 = dxdt(w3s);
        float w4s = vcur + dt * k3;
        stage(w4s); __syncthreads();
        float k4 = dxdt(w4s);
        vcur += dt * (1.0f / 6.0f) * (k1 + 2.0f * k2 + 2.0f * k3 + k4);
        stage(vcur); __syncthreads();
    }

    // t=1 plane
    out[(size_t)BATCH * DATA_DIM + (size_t)b * DATA_DIM + (p - 1)] = vcur;
}

// ---------------------------------------------------------------------------
// kernel_launch
// ---------------------------------------------------------------------------
extern "C" void kernel_launch(void* const* d_in, const int* in_sizes, int n_in,
                              void* d_out, int out_size) {
    const float* t     = (const float*)d_in[0];
    const float* x     = (const float*)d_in[1];
    const float* embed = (const float*)d_in[2];
    const float* Wq    = (const float*)d_in[3];
    const float* bq    = (const float*)d_in[4];
    const float* Wk    = (const float*)d_in[5];
    const float* bk    = (const float*)d_in[6];
    float* out = (float*)d_out;

    precompute_kernel<<<(DATA_DIM + 1 + 31) / 32, 256>>>(embed, Wq, bq, Wk, bk);
    integrate_kernel<<<BATCH, 256>>>(t, x, Wq, Wk, out);
}

// round 13
// speedup vs baseline: 1.7631x; 1.0004x over previous
#include <cuda_runtime.h>
#include <cstddef>

#define BATCH    256
#define DATA_DIM 8192
#define NNZ      256
#define QK       64
#define EMB      63
#define NSUB     8
#define WTS      68
#define WPS      68    // padded stride for w staging segments (4 banks apart -> conflict-free)

typedef unsigned long long u64;

// Precomputed per-row projections of the embedding table (row 0 = padding row).
__device__ float4 g_Q0T[(DATA_DIM + 1) * 16];
__device__ float4 g_K0T[(DATA_DIM + 1) * 16];

// packed f32x2 FMA: acc = a*b + acc
__device__ __forceinline__ void fma2(u64& acc, u64 a, u64 b) {
    asm("fma.rn.f32x2 %0, %1, %2, %0;" : "+l"(acc) : "l"(a), "l"(b));
}
__device__ __forceinline__ float hsum2(u64 a) {
    return __uint_as_float((unsigned)a) + __uint_as_float((unsigned)(a >> 32));
}
__device__ __forceinline__ u64 pack2(float lo, float hi) {
    u64 r;
    asm("mov.b64 %0, {%1, %2};" : "=l"(r) : "f"(lo), "f"(hi));
    return r;
}

// ---------------------------------------------------------------------------
// Kernel P: 129 blocks x 64 table rows, one wave. W transposed to shared once
// per block; embed staged in two 32-row halves (static smem <= 48KB).
// Inner math order BIT-IDENTICAL to the proven version.
// Q0T[p][d] = bq[d] + sum_e embed[p][e] * Wq[d][e+1]   (same for K)
// ---------------------------------------------------------------------------
__global__ void __launch_bounds__(256)
precompute_kernel(const float* __restrict__ embed,
                  const float* __restrict__ Wq,
                  const float* __restrict__ bq,
                  const float* __restrict__ Wk,
                  const float* __restrict__ bk) {
    __shared__ __align__(16) float WqT[64 * WTS];
    __shared__ __align__(16) float WkT[64 * WTS];
    __shared__ __align__(16) float es[32][64];

    const int tid = threadIdx.x;
    for (int i = tid; i < 4096; i += 256) {
        int d = i >> 6, e = i & 63;
        WqT[e * WTS + d] = Wq[i];
        WkT[e * WTS + d] = Wk[i];
    }
    const int p0 = blockIdx.x * 64;
    const int rl = tid >> 4, d4 = tid & 15;
    const float4 bq4 = __ldg(reinterpret_cast<const float4*>(bq) + d4);
    const float4 bk4 = __ldg(reinterpret_cast<const float4*>(bk) + d4);

#pragma unroll
    for (int half = 0; half < 2; ++half) {
        const int ph = p0 + half * 32;
        // stage 32 embed rows (sync guards es reuse across halves)
        __syncthreads();
        for (int i = tid; i < 32 * 63; i += 256) {
            int r = i / 63, e = i - r * 63;
            int p = ph + r;
            es[r][e] = (p <= DATA_DIM) ? embed[(size_t)p * EMB + e] : 0.0f;
        }
        __syncthreads();

#pragma unroll
        for (int grp = 0; grp < 2; ++grp) {
            const int r = grp * 16 + rl;
            const int p = ph + r;
            if (p <= DATA_DIM) {
                float4 aq = bq4, ak = bk4;
#pragma unroll 9
                for (int e = 0; e < EMB; ++e) {
                    float ev = es[r][e];
                    float4 wq = *reinterpret_cast<const float4*>(&WqT[(e + 1) * WTS + 4 * d4]);
                    float4 wk = *reinterpret_cast<const float4*>(&WkT[(e + 1) * WTS + 4 * d4]);
                    aq.x += ev * wq.x; aq.y += ev * wq.y; aq.z += ev * wq.z; aq.w += ev * wq.w;
                    ak.x += ev * wk.x; ak.y += ev * wk.y; ak.z += ev * wk.z; ak.w += ev * wk.w;
                }
                g_Q0T[(size_t)p * 16 + d4] = aq;
                g_K0T[(size_t)p * 16 + d4] = ak;
            }
        }
    }
}

// ---------------------------------------------------------------------------
// Kernel C: FROZEN R11 (best-known). 256 threads, 1 block/SM, q0 row + k0
// column register-resident, coalesced LDG k0 gather, padded w staging.
// ---------------------------------------------------------------------------
__global__ void __launch_bounds__(256, 1)
integrate_kernel(const float* __restrict__ t,
                 const float* __restrict__ x,
                 const float* __restrict__ Wq,
                 const float* __restrict__ Wk,
                 float* __restrict__ out) {
    __shared__ __align__(16) float wsh[4 * WPS];   // padded w staging
    __shared__ __align__(16) float ssh[QK];
    __shared__ __align__(16) float mpart[256];
    __shared__ __align__(16) float red1[8];        // per-warp w^2 partials
    __shared__ __align__(16) float red2[8];        // per-warp w*f partials
    __shared__ __align__(16) float c1p[2];         // a.s partials
    __shared__ __align__(16) float val[NNZ];
    __shared__ int idx[NNZ];
    __shared__ int wscan[8];

    const int tid  = threadIdx.x;
    const int b    = blockIdx.x;
    const int lane = tid & 31;
    const int wid  = tid >> 5;

    // ---- Phase 0: zero this block's two output rows ----
    {
        float4 z = make_float4(0.f, 0.f, 0.f, 0.f);
        float4* o4 = reinterpret_cast<float4*>(out);
        for (int i = tid; i < 2048; i += 256) {
            o4[(size_t)b * 2048 + i] = z;
            o4[(size_t)(BATCH + b) * 2048 + i] = z;
        }
    }

    // ---- Phase 1: scan + order-preserving compaction ----
    float xr[32];
    {
        const float4* xrow4 = reinterpret_cast<const float4*>(x + (size_t)b * DATA_DIM) + tid * 8;
#pragma unroll
        for (int j = 0; j < 8; ++j) {
            float4 f = xrow4[j];
            xr[4 * j + 0] = f.x; xr[4 * j + 1] = f.y;
            xr[4 * j + 2] = f.z; xr[4 * j + 3] = f.w;
        }
    }
    if (tid < NNZ) { val[tid] = 0.0f; idx[tid] = 0; }

    int cnt = 0;
#pragma unroll
    for (int j = 0; j < 32; ++j) cnt += (xr[j] != 0.0f) ? 1 : 0;
    int inc = cnt;
#pragma unroll
    for (int o = 1; o < 32; o <<= 1) {
        int u = __shfl_up_sync(0xffffffffu, inc, o);
        if (lane >= o) inc += u;
    }
    if (lane == 31) wscan[wid] = inc;
    __syncthreads();
    int woff = 0;
#pragma unroll
    for (int wdx = 0; wdx < 8; ++wdx) woff += (wdx < wid) ? wscan[wdx] : 0;
    int o = woff + inc - cnt;
#pragma unroll
    for (int j = 0; j < 32; ++j) {
        float v = xr[j];
        if (v != 0.0f && o < NNZ) {
            val[o] = v;
            idx[o] = tid * 32 + j;
            ++o;
        }
    }
    __syncthreads();

    // ---- Phase 2: q0 row -> regs; k0 column -> regs via coalesced LDG ----
    const int p     = idx[tid] + 1;
    const float myv = val[tid];

    out[(size_t)b * DATA_DIM + (p - 1)] = myv;   // t=0 plane

    u64 q0p[32];   // my row of Q0 (64 floats as 32 packed pairs, sequential)
    {
        const ulonglong2* qrow = reinterpret_cast<const ulonglong2*>(g_Q0T + (size_t)p * 16);
#pragma unroll
        for (int i = 0; i < 16; ++i) {
            ulonglong2 v = qrow[i];
            q0p[2 * i] = v.x; q0p[2 * i + 1] = v.y;
        }
    }

    const int dd = tid & 63, cc = tid >> 6;

    // k0 column chunk K0[p_j][dd], j in [64cc, 64cc+64) -> 32 packed pairs
    u64 k0u[32];
    {
        const float* k0g = reinterpret_cast<const float*>(g_K0T);
        const int jb = cc * 64;
#pragma unroll
        for (int j = 0; j < 32; ++j) {
            int pa = idx[jb + 2 * j] + 1;
            int pb = idx[jb + 2 * j + 1] + 1;
            float fa = __ldg(k0g + (size_t)pa * 64 + dd);
            float fb = __ldg(k0g + (size_t)pb * 64 + dd);
            k0u[j] = pack2(fa, fb);
        }
    }

    float avd = 0.0f, bvd = 0.0f;
    if (tid < QK) { avd = Wq[tid * 64]; bvd = Wk[tid * 64]; }

    const float dt = (t[1] - t[0]) * (1.0f / (float)NSUB);
    const ulonglong2* wvp = reinterpret_cast<const ulonglong2*>(wsh + cc * WPS);
    const ulonglong2* svp = reinterpret_cast<const ulonglong2*>(ssh);

    // stage: publish w (padded segment layout) + per-warp w^2 partial.
    auto stage = [&](float w) {
        wsh[cc * WPS + dd] = w;
        float w2 = w * w;
#pragma unroll
        for (int o2 = 16; o2 > 0; o2 >>= 1) w2 += __shfl_xor_sync(0xffffffffu, w2, o2);
        if (lane == 0) red1[wid] = w2;
    };

    auto dxdt = [&](float w) -> float {
        u64 a0 = 0ull, a1 = 0ull;
#pragma unroll
        for (int m = 0; m < 16; ++m) {
            ulonglong2 wv = wvp[m];
            fma2(a0, k0u[2 * m], wv.x);
            fma2(a1, k0u[2 * m + 1], wv.y);
        }
        mpart[tid] = hsum2(a0) + hsum2(a1);
        __syncthreads();                                   // BAR A

        if (tid < QK) {
            float4 r1a = *reinterpret_cast<const float4*>(&red1[0]);
            float4 r1b = *reinterpret_cast<const float4*>(&red1[4]);
            float S2 = (r1a.x + r1a.y) + (r1a.z + r1a.w) + (r1b.x + r1b.y) + (r1b.z + r1b.w);
            float m = mpart[tid] + mpart[tid + 64] +
                      mpart[tid + 128] + mpart[tid + 192];
            float sv = S2 * bvd + m;
            ssh[tid] = sv;
            float cp = avd * sv;
#pragma unroll
            for (int o2 = 16; o2 > 0; o2 >>= 1) cp += __shfl_xor_sync(0xffffffffu, cp, o2);
            if (lane == 0) c1p[wid] = cp;                  // wid = 0 or 1
        }
        __syncthreads();                                   // BAR B

        u64 q0 = 0ull, q1 = 0ull;
#pragma unroll
        for (int m = 0; m < 16; ++m) {
            ulonglong2 sv = svp[m];
            fma2(q0, q0p[2 * m], sv.x);
            fma2(q1, q0p[2 * m + 1], sv.y);
        }
        float qdot = hsum2(q0) + hsum2(q1);
        float c1 = c1p[0] + c1p[1];
        float f  = (c1 * w + qdot) * 0.125f;               // 1/sqrt(64)

        float wf = w * f;
#pragma unroll
        for (int o2 = 16; o2 > 0; o2 >>= 1) wf += __shfl_xor_sync(0xffffffffu, wf, o2);
        if (lane == 0) red2[wid] = wf;
        __syncthreads();                                   // BAR C
        float4 r2a = *reinterpret_cast<const float4*>(&red2[0]);
        float4 r2b = *reinterpret_cast<const float4*>(&red2[4]);
        float g = (r2a.x + r2a.y) + (r2a.z + r2a.w) + (r2b.x + r2b.y) + (r2b.z + r2b.w);

        return w * (f - g);
    };

    float vcur = myv;
    stage(vcur);
    __syncthreads();

    // ---- Phase 3: 8 RK4 substeps over [t0, t1] ----
    for (int stp = 0; stp < NSUB; ++stp) {
        float k1 = dxdt(vcur);
        float w2s = vcur + 0.5f * dt * k1;
        stage(w2s); __syncthreads();
        float k2 = dxdt(w2s);
        float w3s = vcur + 0.5f * dt * k2;
        stage(w3s); __syncthreads();
        float k3 = dxdt(w3s);
        float w4s = vcur + dt * k3;
        stage(w4s); __syncthreads();
        float k4 = dxdt(w4s);
        vcur += dt * (1.0f / 6.0f) * (k1 + 2.0f * k2 + 2.0f * k3 + k4);
        stage(vcur); __syncthreads();
    }

    // t=1 plane
    out[(size_t)BATCH * DATA_DIM + (size_t)b * DATA_DIM + (p - 1)] = vcur;
}

// ---------------------------------------------------------------------------
// kernel_launch
// ---------------------------------------------------------------------------
extern "C" void kernel_launch(void* const* d_in, const int* in_sizes, int n_in,
                              void* d_out, int out_size) {
    const float* t     = (const float*)d_in[0];
    const float* x     = (const float*)d_in[1];
    const float* embed = (const float*)d_in[2];
    const float* Wq    = (const float*)d_in[3];
    const float* bq    = (const float*)d_in[4];
    const float* Wk    = (const float*)d_in[5];
    const float* bk    = (const float*)d_in[6];
    float* out = (float*)d_out;

    precompute_kernel<<<(DATA_DIM + 1 + 63) / 64, 256>>>(embed, Wq, bq, Wk, bk);
    integrate_kernel<<<BATCH, 256>>>(t, x, Wq, Wk, out);
}

// round 14
// speedup vs baseline: 1.8159x; 1.0300x over previous
#include <cuda_runtime.h>
#include <cstddef>

#define BATCH    256
#define DATA_DIM 8192
#define NNZ      256
#define QK       64
#define EMB      63
#define NSUB     8
#define WTS      68
#define WPS      68    // padded stride for w staging segments (4 banks apart -> conflict-free)

typedef unsigned long long u64;

// Precomputed per-row projections of the embedding table (row 0 = padding row).
__device__ float4 g_Q0T[(DATA_DIM + 1) * 16];
__device__ float4 g_K0T[(DATA_DIM + 1) * 16];

// packed f32x2 FMA: acc = a*b + acc
__device__ __forceinline__ void fma2(u64& acc, u64 a, u64 b) {
    asm("fma.rn.f32x2 %0, %1, %2, %0;" : "+l"(acc) : "l"(a), "l"(b));
}
__device__ __forceinline__ float hsum2(u64 a) {
    return __uint_as_float((unsigned)a) + __uint_as_float((unsigned)(a >> 32));
}
__device__ __forceinline__ u64 pack2(float lo, float hi) {
    u64 r;
    asm("mov.b64 %0, {%1, %2};" : "=l"(r) : "f"(lo), "f"(hi));
    return r;
}

// ---------------------------------------------------------------------------
// Kernel P: 129 blocks x 64 table rows, one wave (R13, proven).
// Q0T[p][d] = bq[d] + sum_e embed[p][e] * Wq[d][e+1]   (same for K)
// ---------------------------------------------------------------------------
__global__ void __launch_bounds__(256)
precompute_kernel(const float* __restrict__ embed,
                  const float* __restrict__ Wq,
                  const float* __restrict__ bq,
                  const float* __restrict__ Wk,
                  const float* __restrict__ bk) {
    __shared__ __align__(16) float WqT[64 * WTS];
    __shared__ __align__(16) float WkT[64 * WTS];
    __shared__ __align__(16) float es[32][64];

    const int tid = threadIdx.x;
    for (int i = tid; i < 4096; i += 256) {
        int d = i >> 6, e = i & 63;
        WqT[e * WTS + d] = Wq[i];
        WkT[e * WTS + d] = Wk[i];
    }
    const int p0 = blockIdx.x * 64;
    const int rl = tid >> 4, d4 = tid & 15;
    const float4 bq4 = __ldg(reinterpret_cast<const float4*>(bq) + d4);
    const float4 bk4 = __ldg(reinterpret_cast<const float4*>(bk) + d4);

#pragma unroll
    for (int half = 0; half < 2; ++half) {
        const int ph = p0 + half * 32;
        __syncthreads();
        for (int i = tid; i < 32 * 63; i += 256) {
            int r = i / 63, e = i - r * 63;
            int p = ph + r;
            es[r][e] = (p <= DATA_DIM) ? embed[(size_t)p * EMB + e] : 0.0f;
        }
        __syncthreads();

#pragma unroll
        for (int grp = 0; grp < 2; ++grp) {
            const int r = grp * 16 + rl;
            const int p = ph + r;
            if (p <= DATA_DIM) {
                float4 aq = bq4, ak = bk4;
#pragma unroll 9
                for (int e = 0; e < EMB; ++e) {
                    float ev = es[r][e];
                    float4 wq = *reinterpret_cast<const float4*>(&WqT[(e + 1) * WTS + 4 * d4]);
                    float4 wk = *reinterpret_cast<const float4*>(&WkT[(e + 1) * WTS + 4 * d4]);
                    aq.x += ev * wq.x; aq.y += ev * wq.y; aq.z += ev * wq.z; aq.w += ev * wq.w;
                    ak.x += ev * wk.x; ak.y += ev * wk.y; ak.z += ev * wk.z; ak.w += ev * wk.w;
                }
                g_Q0T[(size_t)p * 16 + d4] = aq;
                g_K0T[(size_t)p * 16 + d4] = ak;
            }
        }
    }
}

// ---------------------------------------------------------------------------
// Kernel C: R11 base + chain surgery.
//  - w^2 folded into the m-loop (S2 via chunk partials) -> stage is a bare STS
//  - s-step distributed across all 8 warps (lanes 0-7 own d = 8*wid+lane),
//    c1 tree 3 levels instead of 5
// ---------------------------------------------------------------------------
__global__ void __launch_bounds__(256, 1)
integrate_kernel(const float* __restrict__ t,
                 const float* __restrict__ x,
                 const float* __restrict__ Wq,
                 const float* __restrict__ Wk,
                 float* __restrict__ out) {
    __shared__ __align__(16) float wsh[4 * WPS];   // padded w staging
    __shared__ __align__(16) float ssh[QK];
    __shared__ __align__(16) float mpart[256];
    __shared__ __align__(16) float m2part[256];    // w^2 chunk partials
    __shared__ __align__(16) float red2[8];        // per-warp w*f partials
    __shared__ __align__(16) float c1p[8];         // per-warp a.s partials
    __shared__ __align__(16) float val[NNZ];
    __shared__ int idx[NNZ];
    __shared__ int wscan[8];

    const int tid  = threadIdx.x;
    const int b    = blockIdx.x;
    const int lane = tid & 31;
    const int wid  = tid >> 5;

    // ---- Phase 0: zero this block's two output rows ----
    {
        float4 z = make_float4(0.f, 0.f, 0.f, 0.f);
        float4* o4 = reinterpret_cast<float4*>(out);
        for (int i = tid; i < 2048; i += 256) {
            o4[(size_t)b * 2048 + i] = z;
            o4[(size_t)(BATCH + b) * 2048 + i] = z;
        }
    }

    // ---- Phase 1: scan + order-preserving compaction ----
    float xr[32];
    {
        const float4* xrow4 = reinterpret_cast<const float4*>(x + (size_t)b * DATA_DIM) + tid * 8;
#pragma unroll
        for (int j = 0; j < 8; ++j) {
            float4 f = xrow4[j];
            xr[4 * j + 0] = f.x; xr[4 * j + 1] = f.y;
            xr[4 * j + 2] = f.z; xr[4 * j + 3] = f.w;
        }
    }
    if (tid < NNZ) { val[tid] = 0.0f; idx[tid] = 0; }

    int cnt = 0;
#pragma unroll
    for (int j = 0; j < 32; ++j) cnt += (xr[j] != 0.0f) ? 1 : 0;
    int inc = cnt;
#pragma unroll
    for (int o = 1; o < 32; o <<= 1) {
        int u = __shfl_up_sync(0xffffffffu, inc, o);
        if (lane >= o) inc += u;
    }
    if (lane == 31) wscan[wid] = inc;
    __syncthreads();
    int woff = 0;
#pragma unroll
    for (int wdx = 0; wdx < 8; ++wdx) woff += (wdx < wid) ? wscan[wdx] : 0;
    int o = woff + inc - cnt;
#pragma unroll
    for (int j = 0; j < 32; ++j) {
        float v = xr[j];
        if (v != 0.0f && o < NNZ) {
            val[o] = v;
            idx[o] = tid * 32 + j;
            ++o;
        }
    }
    __syncthreads();

    // ---- Phase 2: q0 row -> regs; k0 column -> regs via coalesced LDG ----
    const int p     = idx[tid] + 1;
    const float myv = val[tid];

    out[(size_t)b * DATA_DIM + (p - 1)] = myv;   // t=0 plane

    u64 q0p[32];   // my row of Q0 (64 floats as 32 packed pairs, sequential)
    {
        const ulonglong2* qrow = reinterpret_cast<const ulonglong2*>(g_Q0T + (size_t)p * 16);
#pragma unroll
        for (int i = 0; i < 16; ++i) {
            ulonglong2 v = qrow[i];
            q0p[2 * i] = v.x; q0p[2 * i + 1] = v.y;
        }
    }

    const int dd = tid & 63, cc = tid >> 6;

    // k0 column chunk K0[p_j][dd], j in [64cc, 64cc+64) -> 32 packed pairs
    u64 k0u[32];
    {
        const float* k0g = reinterpret_cast<const float*>(g_K0T);
        const int jb = cc * 64;
#pragma unroll
        for (int j = 0; j < 32; ++j) {
            int pa = idx[jb + 2 * j] + 1;
            int pb = idx[jb + 2 * j + 1] + 1;
            float fa = __ldg(k0g + (size_t)pa * 64 + dd);
            float fb = __ldg(k0g + (size_t)pb * 64 + dd);
            k0u[j] = pack2(fa, fb);
        }
    }

    // s-step role: d = 8*wid + (lane&7); lanes 8-31 are redundant replicas
    // (broadcast reads, identical math), only lanes 0-7 write.
    const int dsg = 8 * wid + (lane & 7);
    const float avd = Wq[dsg * 64];     // a_d
    const float bvd = Wk[dsg * 64];     // b_d

    const float dt = (t[1] - t[0]) * (1.0f / (float)NSUB);
    const ulonglong2* wvp = reinterpret_cast<const ulonglong2*>(wsh + cc * WPS);
    const ulonglong2* svp = reinterpret_cast<const ulonglong2*>(ssh);

    // stage: bare STS (w^2 now computed inside the m-loop)
    auto stage = [&](float w) {
        wsh[cc * WPS + dd] = w;
    };

    // dxdt(w) = w*(f - g);  s = S2*b + K0^T w;  f_i = (c1*w_i + q0_i.s)/8;
    // c1 = a.s;  g = sum_j w_j f_j.  precondition: stage(w) + sync done.
    auto dxdt = [&](float w) -> float {
        // m and w^2 partials over chunk cc (register FMAs, broadcast w reads)
        u64 a0 = 0ull, a1 = 0ull, s0 = 0ull, s1 = 0ull;
#pragma unroll
        for (int m = 0; m < 16; ++m) {
            ulonglong2 wv = wvp[m];
            fma2(a0, k0u[2 * m], wv.x);
            fma2(a1, k0u[2 * m + 1], wv.y);
            fma2(s0, wv.x, wv.x);
            fma2(s1, wv.y, wv.y);
        }
        mpart[tid]  = hsum2(a0) + hsum2(a1);
        m2part[tid] = hsum2(s0) + hsum2(s1);
        __syncthreads();                                   // BAR A

        // distributed s-step (all warps; lanes 8+ redundant via broadcast)
        {
            float m  = mpart[dsg]  + mpart[dsg + 64]  +
                       mpart[dsg + 128]  + mpart[dsg + 192];
            float S2 = m2part[dsg] + m2part[dsg + 64] +
                       m2part[dsg + 128] + m2part[dsg + 192];
            float sv = S2 * bvd + m;
            if ((lane & 24) == 0 && lane < 8) ssh[dsg] = sv;
            float cp = avd * sv;
            cp += __shfl_xor_sync(0xffffffffu, cp, 1);
            cp += __shfl_xor_sync(0xffffffffu, cp, 2);
            cp += __shfl_xor_sync(0xffffffffu, cp, 4);
            if (lane == 0) c1p[wid] = cp;
        }
        __syncthreads();                                   // BAR B

        u64 q0 = 0ull, q1 = 0ull;
#pragma unroll
        for (int m = 0; m < 16; ++m) {
            ulonglong2 sv = svp[m];
            fma2(q0, q0p[2 * m], sv.x);
            fma2(q1, q0p[2 * m + 1], sv.y);
        }
        float qdot = hsum2(q0) + hsum2(q1);
        float4 cpa = *reinterpret_cast<const float4*>(&c1p[0]);
        float4 cpb = *reinterpret_cast<const float4*>(&c1p[4]);
        float c1 = (cpa.x + cpa.y) + (cpa.z + cpa.w) + (cpb.x + cpb.y) + (cpb.z + cpb.w);
        float f  = (c1 * w + qdot) * 0.125f;               // 1/sqrt(64)

        float wf = w * f;
#pragma unroll
        for (int o2 = 16; o2 > 0; o2 >>= 1) wf += __shfl_xor_sync(0xffffffffu, wf, o2);
        if (lane == 0) red2[wid] = wf;
        __syncthreads();                                   // BAR C
        float4 r2a = *reinterpret_cast<const float4*>(&red2[0]);
        float4 r2b = *reinterpret_cast<const float4*>(&red2[4]);
        float g = (r2a.x + r2a.y) + (r2a.z + r2a.w) + (r2b.x + r2b.y) + (r2b.z + r2b.w);

        return w * (f - g);
    };

    float vcur = myv;
    stage(vcur);
    __syncthreads();

    // ---- Phase 3: 8 RK4 substeps over [t0, t1] ----
    for (int stp = 0; stp < NSUB; ++stp) {
        float k1 = dxdt(vcur);
        float w2s = vcur + 0.5f * dt * k1;
        stage(w2s); __syncthreads();
        float k2 = dxdt(w2s);
        float w3s = vcur + 0.5f * dt * k2;
        stage(w3s); __syncthreads();
        float k3 = dxdt(w3s);
        float w4s = vcur + dt * k3;
        stage(w4s); __syncthreads();
        float k4 = dxdt(w4s);
        vcur += dt * (1.0f / 6.0f) * (k1 + 2.0f * k2 + 2.0f * k3 + k4);
        stage(vcur); __syncthreads();
    }

    // t=1 plane
    out[(size_t)BATCH * DATA_DIM + (size_t)b * DATA_DIM + (p - 1)] = vcur;
}

// ---------------------------------------------------------------------------
// kernel_launch
// ---------------------------------------------------------------------------
extern "C" void kernel_launch(void* const* d_in, const int* in_sizes, int n_in,
                              void* d_out, int out_size) {
    const float* t     = (const float*)d_in[0];
    const float* x     = (const float*)d_in[1];
    const float* embed = (const float*)d_in[2];
    const float* Wq    = (const float*)d_in[3];
    const float* bq    = (const float*)d_in[4];
    const float* Wk    = (const float*)d_in[5];
    const float* bk    = (const float*)d_in[6];
    float* out = (float*)d_out;

    precompute_kernel<<<(DATA_DIM + 1 + 63) / 64, 256>>>(embed, Wq, bq, Wk, bk);
    integrate_kernel<<<BATCH, 256>>>(t, x, Wq, Wk, out);
}